// round 1
// baseline (speedup 1.0000x reference)
#include <cuda_runtime.h>

#define NB 16
#define SEQL 20
#define HND 512
#define EMBD 300
#define VD 256
#define PPOS 1024
#define MR (NB*PPOS)   // 16384

// ---------------- device global scratch (no runtime alloc allowed) ----------
__device__ __align__(16) float g_feat[NB*VD*PPOS];     // NCHW working feature
__device__ __align__(16) float g_base[MR*VD];          // per-step-invariant conv part [np][co]
__device__ __align__(16) float g_spart[VD*PPOS];       // spatial conv part [co][p]
__device__ __align__(16) float g_whs[9*VD*HND];        // masked hn-weight sums [t][co][c]
__device__ __align__(16) float g_hnp[NB*VD*9];         // hn conv part [n][co][t]
__device__ __align__(16) float g_Wr[9*VD*VD];          // conv feat weights [tap][ci][co]
__device__ __align__(16) float g_WkvT[VD*2*VD];        // [k][512]
__device__ __align__(16) float g_WoT[VD*VD];
__device__ __align__(16) float g_W1T[VD*VD];
__device__ __align__(16) float g_W2T[VD*VD];
__device__ __align__(16) float g_qh[NB*VD];
__device__ __align__(16) float g_t[MR*VD];             // relu(conv+base)
__device__ __align__(16) float g_tn[MR*VD];            // layernormed t
__device__ __align__(16) float g_kv[MR*2*VD];
__device__ __align__(16) float g_o[MR*VD];
__device__ __align__(16) float g_u[MR*VD];
__device__ __align__(16) float g_fea[MR*VD];
__device__ __align__(16) float g_f1[MR*VD];
__device__ __align__(16) float g_u2[MR*VD];
__device__ __align__(16) float g_fea2[MR*VD];

// ---------------- prep kernels ----------------------------------------------

__global__ void k_copy_feat(const float4* __restrict__ src) {
    int i = blockIdx.x * 256 + threadIdx.x;             // 4096*256 = 1,048,576 float4
    reinterpret_cast<float4*>(g_feat)[i] = src[i];
}

__global__ void k_copyout(float4* __restrict__ dst) {
    int i = blockIdx.x * 256 + threadIdx.x;
    dst[i] = reinterpret_cast<const float4*>(g_feat)[i];
}

// reorder conv feat weights: g_Wr[(tap*256+ci)*256+co] = W[co][ci][tap]
__global__ void k_wr(const float* __restrict__ W) {
    int idx = blockIdx.x * 256 + threadIdx.x;
    if (idx >= 9 * VD * VD) return;
    int co  = idx & 255;
    int ci  = (idx >> 8) & 255;
    int tap = idx >> 16;
    g_Wr[idx] = W[(co * 776 + ci) * 9 + tap];
}

// masked hn weight sums per border-region type t = ry*3+rx
__global__ void k_whs(const float* __restrict__ W) {
    int idx = blockIdx.x * 256 + threadIdx.x;
    if (idx >= 9 * VD * HND) return;
    int c  = idx & 511;
    int co = (idx >> 9) & 255;
    int t  = idx >> 17;
    int ry = t / 3, rx = t % 3;
    float s = 0.f;
    const float* w = &W[(co * 776 + 264 + c) * 9];
    #pragma unroll
    for (int ky = 0; ky < 3; ky++) {
        if ((ry == 0 && ky == 0) || (ry == 2 && ky == 2)) continue;
        #pragma unroll
        for (int kx = 0; kx < 3; kx++) {
            if ((rx == 0 && kx == 0) || (rx == 2 && kx == 2)) continue;
            s += w[ky * 3 + kx];
        }
    }
    g_whs[idx] = s;
}

// dst[k*NN+j] = src[j*256+k]
__global__ void k_transpose(float* __restrict__ dst, const float* __restrict__ src, int NN) {
    int idx = blockIdx.x * 256 + threadIdx.x;
    if (idx >= NN * 256) return;
    int j = idx / 256;
    int k = idx % 256;
    dst[k * NN + j] = src[idx];
}

// g_hnp[(n*256+co)*9+t] = sum_c hn[n,c] * g_whs[(t*256+co)*512+c]
__global__ void k_hnp(const float* __restrict__ hn) {
    int idx = blockIdx.x * 256 + threadIdx.x;
    if (idx >= NB * VD * 9) return;
    int t  = idx % 9;
    int co = (idx / 9) % 256;
    int n  = idx / (9 * 256);
    const float* h = &hn[n * HND];
    const float* w = &g_whs[(t * 256 + co) * HND];
    float s = 0.f;
    for (int c = 0; c < HND; c++) s += h[c] * w[c];
    g_hnp[idx] = s;
}

// spatial conv part, direct 8-channel conv with inline spatial features
__global__ void k_spart(const float* __restrict__ W) {
    int idx = blockIdx.x * 256 + threadIdx.x;   // co*1024 + p
    if (idx >= VD * PPOS) return;
    int p = idx & 1023, co = idx >> 10;
    int y = p >> 5, x = p & 31;
    float s = 0.f;
    #pragma unroll
    for (int ky = 0; ky < 3; ky++) {
        int yy = y + ky - 1;
        if (yy < 0 || yy > 31) continue;
        #pragma unroll
        for (int kx = 0; kx < 3; kx++) {
            int xx = x + kx - 1;
            if (xx < 0 || xx > 31) continue;
            const float* w = &W[(co * 776 + 256) * 9 + ky * 3 + kx]; // channel stride 9
            float fx = (float)xx, fy = (float)yy;
            float xmin = fx * 0.0625f - 1.f;
            float xmax = (fx + 1.f) * 0.0625f - 1.f;
            float ymin = fy * 0.0625f - 1.f;
            float ymax = (fy + 1.f) * 0.0625f - 1.f;
            s += w[0]  * xmin + w[9]  * ymin + w[18] * xmax + w[27] * ymax
               + w[36] * (0.5f * (xmin + xmax)) + w[45] * (0.5f * (ymin + ymax))
               + w[54] * 0.03125f + w[63] * 0.03125f;
        }
    }
    g_spart[idx] = s;
}

__global__ void k_base() {
    int idx = blockIdx.x * 256 + threadIdx.x;   // m*256+co
    int co = idx & 255;
    int m  = idx >> 8;
    int n = m >> 10, p = m & 1023;
    int y = p >> 5, x = p & 31;
    int ry = (y == 0) ? 0 : ((y == 31) ? 2 : 1);
    int rx = (x == 0) ? 0 : ((x == 31) ? 2 : 1);
    g_base[idx] = g_spart[co * 1024 + p] + g_hnp[(n * 256 + co) * 9 + ry * 3 + rx];
}

// ---------------- per-step kernels ------------------------------------------

// q = relu(emb @ qconv_w.T + qconv_b); qh = q @ Wq.T + bq
__global__ void k_qh(const float* __restrict__ emb, const float* __restrict__ qw,
                     const float* __restrict__ qb, const float* __restrict__ ipw,
                     const float* __restrict__ ipb, int s) {
    __shared__ float qs[VD];
    int n = blockIdx.x, v = threadIdx.x;
    const float* e = emb + (n * SEQL + s) * EMBD;
    float a = qb[v];
    const float* wr = &qw[v * EMBD];
    for (int i = 0; i < EMBD; i++) a += e[i] * wr[i];
    qs[v] = fmaxf(a, 0.f);
    __syncthreads();
    float a2 = ipb[v];
    const float* wq = &ipw[v * VD];
    for (int c = 0; c < VD; c++) a2 += qs[c] * wq[c];
    g_qh[n * VD + v] = a2;
}

// implicit-GEMM 3x3 conv over the 256 feat channels; epilogue adds g_base, relu
__global__ void __launch_bounds__(256, 2) k_conv() {
    __shared__ float As[8][128];
    __shared__ float Bs[8][128];
    int tid = threadIdx.x;
    int m0 = blockIdx.x * 128;
    int n  = m0 >> 10;
    int p0 = m0 & 1023;
    int y0 = p0 >> 5;
    int co0 = blockIdx.y * 128;
    int tx = tid & 15, ty = tid >> 4;
    float acc[8][8];
    #pragma unroll
    for (int i = 0; i < 8; i++)
        #pragma unroll
        for (int j = 0; j < 8; j++) acc[i][j] = 0.f;
    const float* fbase = g_feat + n * (VD * PPOS);
    int bkk = tid >> 5, bnn = (tid & 31) << 2;
    for (int kc = 0; kc < 288; kc++) {
        int tap = kc >> 5;
        int ci0 = (kc & 31) << 3;
        int dy = tap / 3 - 1, dx = tap % 3 - 1;
        #pragma unroll
        for (int i = 0; i < 4; i++) {
            int lid = i * 256 + tid;
            int kk = lid >> 7;
            int mm = lid & 127;
            int yy = y0 + (mm >> 5) + dy;
            int xx = (mm & 31) + dx;
            float v = 0.f;
            if (yy >= 0 && yy < 32 && xx >= 0 && xx < 32)
                v = fbase[(ci0 + kk) * 1024 + yy * 32 + xx];
            As[kk][mm] = v;
        }
        float4 bv = *(const float4*)&g_Wr[((tap << 8) + ci0 + bkk) * 256 + co0 + bnn];
        *(float4*)&Bs[bkk][bnn] = bv;
        __syncthreads();
        #pragma unroll
        for (int k = 0; k < 8; k++) {
            float a[8], b[8];
            #pragma unroll
            for (int i = 0; i < 8; i++) a[i] = As[k][ty * 8 + i];
            #pragma unroll
            for (int j = 0; j < 8; j++) b[j] = Bs[k][tx * 8 + j];
            #pragma unroll
            for (int i = 0; i < 8; i++)
                #pragma unroll
                for (int j = 0; j < 8; j++) acc[i][j] += a[i] * b[j];
        }
        __syncthreads();
    }
    #pragma unroll
    for (int i = 0; i < 8; i++) {
        int m = m0 + ty * 8 + i;
        #pragma unroll
        for (int j = 0; j < 8; j++) {
            int c = co0 + tx * 8 + j;
            float v = acc[i][j] + g_base[m * 256 + c];
            g_t[m * 256 + c] = fmaxf(v, 0.f);
        }
    }
}

// generic fp32 GEMM: C = act(A[M,256] @ Bt[256,NN] + bias (+ residual))
template<int NN, bool RELU, bool RES>
__global__ void __launch_bounds__(256, 2) k_gemm(const float* __restrict__ A,
        const float* __restrict__ Bt, const float* __restrict__ bias,
        const float* __restrict__ Rsd, float* __restrict__ C) {
    __shared__ float As[8][128];
    __shared__ float Bs[8][128];
    int tid = threadIdx.x;
    int m0 = blockIdx.x * 128, n0 = blockIdx.y * 128;
    int tx = tid & 15, ty = tid >> 4;
    float acc[8][8];
    #pragma unroll
    for (int i = 0; i < 8; i++)
        #pragma unroll
        for (int j = 0; j < 8; j++) acc[i][j] = 0.f;
    int r = tid >> 1, hq = (tid & 1) * 4;
    int bkk = tid >> 5, bnn = (tid & 31) << 2;
    for (int kc = 0; kc < 32; kc++) {
        int k0 = kc * 8;
        float4 av = *(const float4*)&A[(m0 + r) * 256 + k0 + hq];
        As[hq + 0][r] = av.x; As[hq + 1][r] = av.y;
        As[hq + 2][r] = av.z; As[hq + 3][r] = av.w;
        float4 bv = *(const float4*)&Bt[(k0 + bkk) * NN + n0 + bnn];
        *(float4*)&Bs[bkk][bnn] = bv;
        __syncthreads();
        #pragma unroll
        for (int k = 0; k < 8; k++) {
            float a[8], b[8];
            #pragma unroll
            for (int i = 0; i < 8; i++) a[i] = As[k][ty * 8 + i];
            #pragma unroll
            for (int j = 0; j < 8; j++) b[j] = Bs[k][tx * 8 + j];
            #pragma unroll
            for (int i = 0; i < 8; i++)
                #pragma unroll
                for (int j = 0; j < 8; j++) acc[i][j] += a[i] * b[j];
        }
        __syncthreads();
    }
    #pragma unroll
    for (int i = 0; i < 8; i++) {
        int m = m0 + ty * 8 + i;
        #pragma unroll
        for (int j = 0; j < 8; j++) {
            int c = n0 + tx * 8 + j;
            float v = acc[i][j] + bias[c];
            if (RES) v += Rsd[m * NN + c];
            if (RELU) v = fmaxf(v, 0.f);
            C[m * NN + c] = v;
        }
    }
}

// LayerNorm over 256 channels
__global__ void k_ln(const float* __restrict__ in, float* __restrict__ out,
                     const float* __restrict__ g, const float* __restrict__ b) {
    int row = blockIdx.x, tid = threadIdx.x;
    float x = in[row * 256 + tid];
    float s1 = x, s2 = x * x;
    #pragma unroll
    for (int o = 16; o > 0; o >>= 1) {
        s1 += __shfl_xor_sync(0xffffffffu, s1, o);
        s2 += __shfl_xor_sync(0xffffffffu, s2, o);
    }
    __shared__ float w1[8], w2[8];
    if ((tid & 31) == 0) { w1[tid >> 5] = s1; w2[tid >> 5] = s2; }
    __syncthreads();
    float t1 = 0.f, t2 = 0.f;
    #pragma unroll
    for (int i = 0; i < 8; i++) { t1 += w1[i]; t2 += w2[i]; }
    float mean = t1 * (1.f / 256.f);
    float var  = t2 * (1.f / 256.f) - mean * mean;
    float rr = rsqrtf(var + 1e-5f);
    out[row * 256 + tid] = (x - mean) * rr * g[tid] + b[tid];
}

// batch-wise attention: per position p, per head h: softmax_m(q_l . k_m) @ v_m
__global__ void k_attn() {
    __shared__ float khs[16 * 257];
    __shared__ float qs[16 * 257];
    __shared__ float ss[512];
    int p = blockIdx.x, tid = threadIdx.x;
    #pragma unroll
    for (int m = 0; m < 16; m++)
        khs[m * 257 + tid] = g_kv[((m << 10) + p) * 512 + tid];
    #pragma unroll
    for (int l = 0; l < 16; l++)
        qs[l * 257 + tid] = g_qh[l * 256 + tid];
    __syncthreads();
    const float scale = 0.08838834764831845f;   // 1/sqrt(128)
    #pragma unroll
    for (int it = 0; it < 2; it++) {
        int idx = it * 256 + tid;
        int h = idx >> 8, l = (idx >> 4) & 15, m = idx & 15;
        const float* qv = &qs[l * 257 + h * 128];
        const float* kv = &khs[m * 257 + h * 128];
        float a = 0.f;
        #pragma unroll 8
        for (int d = 0; d < 128; d++) a += qv[d] * kv[d];
        ss[idx] = a * scale;
    }
    __syncthreads();
    if (tid < 32) {
        float* row = &ss[tid * 16];
        float mx = row[0];
        #pragma unroll
        for (int i = 1; i < 16; i++) mx = fmaxf(mx, row[i]);
        float sum = 0.f;
        #pragma unroll
        for (int i = 0; i < 16; i++) { row[i] = expf(row[i] - mx); sum += row[i]; }
        float inv = 1.f / sum;
        #pragma unroll
        for (int i = 0; i < 16; i++) row[i] *= inv;
    }
    __syncthreads();
    int c = tid;
    int h = c >> 7;
    float vv[16];
    #pragma unroll
    for (int m = 0; m < 16; m++)
        vv[m] = g_kv[((m << 10) + p) * 512 + 256 + c];
    #pragma unroll
    for (int l = 0; l < 16; l++) {
        const float* ar = &ss[h * 256 + l * 16];
        float a = 0.f;
        #pragma unroll
        for (int m = 0; m < 16; m++) a += ar[m] * vv[m];
        g_o[((l << 10) + p) * 256 + c] = a;
    }
}

// conditional transposed write-back: feat[n,c,y,x] = fea2[n, p, c] if active
__global__ void k_writeback(const int* __restrict__ words, int s) {
    if (words[s] == 0) return;       // words[0, s]
    __shared__ float tile[32][33];
    int n = blockIdx.x, c0 = blockIdx.y * 32, p0 = blockIdx.z * 32;
    int tid = threadIdx.x;
    int cc = tid & 31, pr = tid >> 5;
    #pragma unroll
    for (int i = 0; i < 4; i++) {
        int pp = i * 8 + pr;
        tile[pp][cc] = g_fea2[(n * 1024 + p0 + pp) * 256 + c0 + cc];
    }
    __syncthreads();
    #pragma unroll
    for (int i = 0; i < 4; i++) {
        int crow = i * 8 + pr;
        g_feat[n * (VD * PPOS) + (c0 + crow) * 1024 + p0 + cc] = tile[cc][crow];
    }
}

// ---------------- launch ------------------------------------------------------

extern "C" void kernel_launch(void* const* d_in, const int* in_sizes, int n_in,
                              void* d_out, int out_size) {
    (void)in_sizes; (void)n_in; (void)out_size;
    const float* hn        = (const float*)d_in[1];
    const float* feature   = (const float*)d_in[2];
    const float* embedding = (const float*)d_in[3];
    const int*   words     = (const int*)  d_in[4];
    const float* qconv_w   = (const float*)d_in[5];
    const float* qconv_b   = (const float*)d_in[6];
    const float* mconv_w   = (const float*)d_in[7];
    const float* mnorm_g   = (const float*)d_in[8];
    const float* mnorm_b   = (const float*)d_in[9];
    const float* in_proj_w = (const float*)d_in[10];
    const float* in_proj_b = (const float*)d_in[11];
    const float* out_proj_w= (const float*)d_in[12];
    const float* out_proj_b= (const float*)d_in[13];
    const float* norm_g    = (const float*)d_in[14];
    const float* norm_b    = (const float*)d_in[15];
    const float* lin1_w    = (const float*)d_in[16];
    const float* lin1_b    = (const float*)d_in[17];
    const float* lin2_w    = (const float*)d_in[18];
    const float* lin2_b    = (const float*)d_in[19];
    const float* normf_g   = (const float*)d_in[20];
    const float* normf_b   = (const float*)d_in[21];

    float *p_WkvT, *p_WoT, *p_W1T, *p_W2T;
    float *p_t, *p_tn, *p_kv, *p_o, *p_u, *p_fea, *p_f1, *p_u2, *p_fea2;
    cudaGetSymbolAddress((void**)&p_WkvT, g_WkvT);
    cudaGetSymbolAddress((void**)&p_WoT,  g_WoT);
    cudaGetSymbolAddress((void**)&p_W1T,  g_W1T);
    cudaGetSymbolAddress((void**)&p_W2T,  g_W2T);
    cudaGetSymbolAddress((void**)&p_t,    g_t);
    cudaGetSymbolAddress((void**)&p_tn,   g_tn);
    cudaGetSymbolAddress((void**)&p_kv,   g_kv);
    cudaGetSymbolAddress((void**)&p_o,    g_o);
    cudaGetSymbolAddress((void**)&p_u,    g_u);
    cudaGetSymbolAddress((void**)&p_fea,  g_fea);
    cudaGetSymbolAddress((void**)&p_f1,   g_f1);
    cudaGetSymbolAddress((void**)&p_u2,   g_u2);
    cudaGetSymbolAddress((void**)&p_fea2, g_fea2);

    // ---- prep (per launch, deterministic) ----
    k_copy_feat<<<4096, 256>>>((const float4*)feature);
    k_wr <<<(9 * VD * VD + 255) / 256, 256>>>(mconv_w);
    k_whs<<<(9 * VD * HND + 255) / 256, 256>>>(mconv_w);
    k_transpose<<<(512 * 256 + 255) / 256, 256>>>(p_WkvT, in_proj_w + 256 * 256, 512);
    k_transpose<<<(256 * 256 + 255) / 256, 256>>>(p_WoT, out_proj_w, 256);
    k_transpose<<<(256 * 256 + 255) / 256, 256>>>(p_W1T, lin1_w, 256);
    k_transpose<<<(256 * 256 + 255) / 256, 256>>>(p_W2T, lin2_w, 256);
    k_hnp  <<<(NB * VD * 9 + 255) / 256, 256>>>(hn);
    k_spart<<<(VD * PPOS + 255) / 256, 256>>>(mconv_w);
    k_base <<<MR * VD / 256, 256>>>();

    // ---- 20 recurrent steps ----
    for (int s = 0; s < SEQL; s++) {
        k_qh<<<NB, 256>>>(embedding, qconv_w, qconv_b, in_proj_w, in_proj_b, s);
        k_conv<<<dim3(128, 2), 256>>>();
        k_ln<<<MR, 256>>>(p_t, p_tn, mnorm_g, mnorm_b);
        k_gemm<512, false, false><<<dim3(128, 4), 256>>>(p_tn, p_WkvT, in_proj_b + 256, nullptr, p_kv);
        k_attn<<<PPOS, 256>>>();
        k_gemm<256, false, true><<<dim3(128, 2), 256>>>(p_o, p_WoT, out_proj_b, p_tn, p_u);
        k_ln<<<MR, 256>>>(p_u, p_fea, norm_g, norm_b);
        k_gemm<256, true, false><<<dim3(128, 2), 256>>>(p_fea, p_W1T, lin1_b, nullptr, p_f1);
        k_gemm<256, false, true><<<dim3(128, 2), 256>>>(p_f1, p_W2T, lin2_b, p_fea, p_u2);
        k_ln<<<MR, 256>>>(p_u2, p_fea2, normf_g, normf_b);
        k_writeback<<<dim3(16, 8, 32), 256>>>(words, s);
    }

    k_copyout<<<4096, 256>>>((float4*)d_out);
}

// round 2
// speedup vs baseline: 1.0004x; 1.0004x over previous
#include <cuda_runtime.h>

#define NB 16
#define SEQL 20
#define HND 512
#define EMBD 300
#define VD 256
#define PPOS 1024
#define MR (NB*PPOS)   // 16384

// ---------------- device global scratch (no runtime alloc allowed) ----------
__device__ __align__(16) float g_feat[NB*VD*PPOS];     // NCHW working feature
__device__ __align__(16) float g_base[MR*VD];          // per-step-invariant conv part [np][co]
__device__ __align__(16) float g_spart[VD*PPOS];       // spatial conv part [co][p]
__device__ __align__(16) float g_whs[9*VD*HND];        // masked hn-weight sums [t][co][c]
__device__ __align__(16) float g_hnp[NB*VD*9];         // hn conv part [n][co][t]
__device__ __align__(16) float g_Wr[9*VD*VD];          // conv feat weights [tap][ci][co]
__device__ __align__(16) float g_WkvT[VD*2*VD];        // [k][512]
__device__ __align__(16) float g_WoT[VD*VD];
__device__ __align__(16) float g_W1T[VD*VD];
__device__ __align__(16) float g_W2T[VD*VD];
__device__ __align__(16) float g_qh[NB*VD];
__device__ __align__(16) float g_t[MR*VD];             // relu(conv+base)
__device__ __align__(16) float g_tn[MR*VD];            // layernormed t
__device__ __align__(16) float g_kv[MR*2*VD];
__device__ __align__(16) float g_o[MR*VD];
__device__ __align__(16) float g_u[MR*VD];
__device__ __align__(16) float g_fea[MR*VD];
__device__ __align__(16) float g_f1[MR*VD];
__device__ __align__(16) float g_u2[MR*VD];
__device__ __align__(16) float g_fea2[MR*VD];

// ---------------- prep kernels ----------------------------------------------

__global__ void k_copy_feat(const float4* __restrict__ src) {
    int i = blockIdx.x * 256 + threadIdx.x;             // 4096*256 = 1,048,576 float4
    reinterpret_cast<float4*>(g_feat)[i] = src[i];
}

__global__ void k_copyout(float4* __restrict__ dst) {
    int i = blockIdx.x * 256 + threadIdx.x;
    dst[i] = reinterpret_cast<const float4*>(g_feat)[i];
}

// reorder conv feat weights: g_Wr[(tap*256+ci)*256+co] = W[co][ci][tap]
__global__ void k_wr(const float* __restrict__ W) {
    int idx = blockIdx.x * 256 + threadIdx.x;
    if (idx >= 9 * VD * VD) return;
    int co  = idx & 255;
    int ci  = (idx >> 8) & 255;
    int tap = idx >> 16;
    g_Wr[idx] = W[(co * 776 + ci) * 9 + tap];
}

// masked hn weight sums per border-region type t = ry*3+rx
__global__ void k_whs(const float* __restrict__ W) {
    int idx = blockIdx.x * 256 + threadIdx.x;
    if (idx >= 9 * VD * HND) return;
    int c  = idx & 511;
    int co = (idx >> 9) & 255;
    int t  = idx >> 17;
    int ry = t / 3, rx = t % 3;
    float s = 0.f;
    const float* w = &W[(co * 776 + 264 + c) * 9];
    #pragma unroll
    for (int ky = 0; ky < 3; ky++) {
        if ((ry == 0 && ky == 0) || (ry == 2 && ky == 2)) continue;
        #pragma unroll
        for (int kx = 0; kx < 3; kx++) {
            if ((rx == 0 && kx == 0) || (rx == 2 && kx == 2)) continue;
            s += w[ky * 3 + kx];
        }
    }
    g_whs[idx] = s;
}

// dst[k*NN+j] = src[j*256+k]
__global__ void k_transpose(float* __restrict__ dst, const float* __restrict__ src, int NN) {
    int idx = blockIdx.x * 256 + threadIdx.x;
    if (idx >= NN * 256) return;
    int j = idx / 256;
    int k = idx % 256;
    dst[k * NN + j] = src[idx];
}

// g_hnp[(n*256+co)*9+t] = sum_c hn[n,c] * g_whs[(t*256+co)*512+c]
__global__ void k_hnp(const float* __restrict__ hn) {
    int idx = blockIdx.x * 256 + threadIdx.x;
    if (idx >= NB * VD * 9) return;
    int t  = idx % 9;
    int co = (idx / 9) % 256;
    int n  = idx / (9 * 256);
    const float* h = &hn[n * HND];
    const float* w = &g_whs[(t * 256 + co) * HND];
    float s = 0.f;
    for (int c = 0; c < HND; c++) s += h[c] * w[c];
    g_hnp[idx] = s;
}

// spatial conv part, direct 8-channel conv with inline spatial features
__global__ void k_spart(const float* __restrict__ W) {
    int idx = blockIdx.x * 256 + threadIdx.x;   // co*1024 + p
    if (idx >= VD * PPOS) return;
    int p = idx & 1023, co = idx >> 10;
    int y = p >> 5, x = p & 31;
    float s = 0.f;
    #pragma unroll
    for (int ky = 0; ky < 3; ky++) {
        int yy = y + ky - 1;
        if (yy < 0 || yy > 31) continue;
        #pragma unroll
        for (int kx = 0; kx < 3; kx++) {
            int xx = x + kx - 1;
            if (xx < 0 || xx > 31) continue;
            const float* w = &W[(co * 776 + 256) * 9 + ky * 3 + kx]; // channel stride 9
            float fx = (float)xx, fy = (float)yy;
            float xmin = fx * 0.0625f - 1.f;
            float xmax = (fx + 1.f) * 0.0625f - 1.f;
            float ymin = fy * 0.0625f - 1.f;
            float ymax = (fy + 1.f) * 0.0625f - 1.f;
            s += w[0]  * xmin + w[9]  * ymin + w[18] * xmax + w[27] * ymax
               + w[36] * (0.5f * (xmin + xmax)) + w[45] * (0.5f * (ymin + ymax))
               + w[54] * 0.03125f + w[63] * 0.03125f;
        }
    }
    g_spart[idx] = s;
}

__global__ void k_base() {
    int idx = blockIdx.x * 256 + threadIdx.x;   // m*256+co
    int co = idx & 255;
    int m  = idx >> 8;
    int n = m >> 10, p = m & 1023;
    int y = p >> 5, x = p & 31;
    int ry = (y == 0) ? 0 : ((y == 31) ? 2 : 1);
    int rx = (x == 0) ? 0 : ((x == 31) ? 2 : 1);
    g_base[idx] = g_spart[co * 1024 + p] + g_hnp[(n * 256 + co) * 9 + ry * 3 + rx];
}

// ---------------- per-step kernels ------------------------------------------

// q = relu(emb @ qconv_w.T + qconv_b); qh = q @ Wq.T + bq
__global__ void k_qh(const float* __restrict__ emb, const float* __restrict__ qw,
                     const float* __restrict__ qb, const float* __restrict__ ipw,
                     const float* __restrict__ ipb, int s) {
    __shared__ float qs[VD];
    int n = blockIdx.x, v = threadIdx.x;
    const float* e = emb + (n * SEQL + s) * EMBD;
    float a = qb[v];
    const float* wr = &qw[v * EMBD];
    for (int i = 0; i < EMBD; i++) a += e[i] * wr[i];
    qs[v] = fmaxf(a, 0.f);
    __syncthreads();
    float a2 = ipb[v];
    const float* wq = &ipw[v * VD];
    for (int c = 0; c < VD; c++) a2 += qs[c] * wq[c];
    g_qh[n * VD + v] = a2;
}

// implicit-GEMM 3x3 conv over the 256 feat channels; epilogue adds g_base, relu
__global__ void __launch_bounds__(256, 2) k_conv() {
    __shared__ float As[8][128];
    __shared__ float Bs[8][128];
    int tid = threadIdx.x;
    int m0 = blockIdx.x * 128;
    int n  = m0 >> 10;
    int p0 = m0 & 1023;
    int y0 = p0 >> 5;
    int co0 = blockIdx.y * 128;
    int tx = tid & 15, ty = tid >> 4;
    float acc[8][8];
    #pragma unroll
    for (int i = 0; i < 8; i++)
        #pragma unroll
        for (int j = 0; j < 8; j++) acc[i][j] = 0.f;
    const float* fbase = g_feat + n * (VD * PPOS);
    int bkk = tid >> 5, bnn = (tid & 31) << 2;
    for (int kc = 0; kc < 288; kc++) {
        int tap = kc >> 5;
        int ci0 = (kc & 31) << 3;
        int dy = tap / 3 - 1, dx = tap % 3 - 1;
        #pragma unroll
        for (int i = 0; i < 4; i++) {
            int lid = i * 256 + tid;
            int kk = lid >> 7;
            int mm = lid & 127;
            int yy = y0 + (mm >> 5) + dy;
            int xx = (mm & 31) + dx;
            float v = 0.f;
            if (yy >= 0 && yy < 32 && xx >= 0 && xx < 32)
                v = fbase[(ci0 + kk) * 1024 + yy * 32 + xx];
            As[kk][mm] = v;
        }
        float4 bv = *(const float4*)&g_Wr[((tap << 8) + ci0 + bkk) * 256 + co0 + bnn];
        *(float4*)&Bs[bkk][bnn] = bv;
        __syncthreads();
        #pragma unroll
        for (int k = 0; k < 8; k++) {
            float a[8], b[8];
            #pragma unroll
            for (int i = 0; i < 8; i++) a[i] = As[k][ty * 8 + i];
            #pragma unroll
            for (int j = 0; j < 8; j++) b[j] = Bs[k][tx * 8 + j];
            #pragma unroll
            for (int i = 0; i < 8; i++)
                #pragma unroll
                for (int j = 0; j < 8; j++) acc[i][j] += a[i] * b[j];
        }
        __syncthreads();
    }
    #pragma unroll
    for (int i = 0; i < 8; i++) {
        int m = m0 + ty * 8 + i;
        #pragma unroll
        for (int j = 0; j < 8; j++) {
            int c = co0 + tx * 8 + j;
            float v = acc[i][j] + g_base[m * 256 + c];
            g_t[m * 256 + c] = fmaxf(v, 0.f);
        }
    }
}

// generic fp32 GEMM: C = act(A[M,256] @ Bt[256,NN] + bias (+ residual))
template<int NN, bool RELU, bool RES>
__global__ void __launch_bounds__(256, 2) k_gemm(const float* __restrict__ A,
        const float* __restrict__ Bt, const float* __restrict__ bias,
        const float* __restrict__ Rsd, float* __restrict__ C) {
    __shared__ float As[8][128];
    __shared__ float Bs[8][128];
    int tid = threadIdx.x;
    int m0 = blockIdx.x * 128, n0 = blockIdx.y * 128;
    int tx = tid & 15, ty = tid >> 4;
    float acc[8][8];
    #pragma unroll
    for (int i = 0; i < 8; i++)
        #pragma unroll
        for (int j = 0; j < 8; j++) acc[i][j] = 0.f;
    int r = tid >> 1, hq = (tid & 1) * 4;
    int bkk = tid >> 5, bnn = (tid & 31) << 2;
    for (int kc = 0; kc < 32; kc++) {
        int k0 = kc * 8;
        float4 av = *(const float4*)&A[(m0 + r) * 256 + k0 + hq];
        As[hq + 0][r] = av.x; As[hq + 1][r] = av.y;
        As[hq + 2][r] = av.z; As[hq + 3][r] = av.w;
        float4 bv = *(const float4*)&Bt[(k0 + bkk) * NN + n0 + bnn];
        *(float4*)&Bs[bkk][bnn] = bv;
        __syncthreads();
        #pragma unroll
        for (int k = 0; k < 8; k++) {
            float a[8], b[8];
            #pragma unroll
            for (int i = 0; i < 8; i++) a[i] = As[k][ty * 8 + i];
            #pragma unroll
            for (int j = 0; j < 8; j++) b[j] = Bs[k][tx * 8 + j];
            #pragma unroll
            for (int i = 0; i < 8; i++)
                #pragma unroll
                for (int j = 0; j < 8; j++) acc[i][j] += a[i] * b[j];
        }
        __syncthreads();
    }
    #pragma unroll
    for (int i = 0; i < 8; i++) {
        int m = m0 + ty * 8 + i;
        #pragma unroll
        for (int j = 0; j < 8; j++) {
            int c = n0 + tx * 8 + j;
            float v = acc[i][j] + bias[c];
            if (RES) v += Rsd[m * NN + c];
            if (RELU) v = fmaxf(v, 0.f);
            C[m * NN + c] = v;
        }
    }
}

// LayerNorm over 256 channels
__global__ void k_ln(const float* __restrict__ in, float* __restrict__ out,
                     const float* __restrict__ g, const float* __restrict__ b) {
    int row = blockIdx.x, tid = threadIdx.x;
    float x = in[row * 256 + tid];
    float s1 = x, s2 = x * x;
    #pragma unroll
    for (int o = 16; o > 0; o >>= 1) {
        s1 += __shfl_xor_sync(0xffffffffu, s1, o);
        s2 += __shfl_xor_sync(0xffffffffu, s2, o);
    }
    __shared__ float w1[8], w2[8];
    if ((tid & 31) == 0) { w1[tid >> 5] = s1; w2[tid >> 5] = s2; }
    __syncthreads();
    float t1 = 0.f, t2 = 0.f;
    #pragma unroll
    for (int i = 0; i < 8; i++) { t1 += w1[i]; t2 += w2[i]; }
    float mean = t1 * (1.f / 256.f);
    float var  = t2 * (1.f / 256.f) - mean * mean;
    float rr = rsqrtf(var + 1e-5f);
    out[row * 256 + tid] = (x - mean) * rr * g[tid] + b[tid];
}

// batch-wise attention: per position p, per head h: softmax_m(q_l . k_m) @ v_m
__global__ void k_attn() {
    __shared__ float khs[16 * 257];
    __shared__ float qs[16 * 257];
    __shared__ float ss[512];
    int p = blockIdx.x, tid = threadIdx.x;
    #pragma unroll
    for (int m = 0; m < 16; m++)
        khs[m * 257 + tid] = g_kv[((m << 10) + p) * 512 + tid];
    #pragma unroll
    for (int l = 0; l < 16; l++)
        qs[l * 257 + tid] = g_qh[l * 256 + tid];
    __syncthreads();
    const float scale = 0.08838834764831845f;   // 1/sqrt(128)
    #pragma unroll
    for (int it = 0; it < 2; it++) {
        int idx = it * 256 + tid;
        int h = idx >> 8, l = (idx >> 4) & 15, m = idx & 15;
        const float* qv = &qs[l * 257 + h * 128];
        const float* kv = &khs[m * 257 + h * 128];
        float a = 0.f;
        #pragma unroll 8
        for (int d = 0; d < 128; d++) a += qv[d] * kv[d];
        ss[idx] = a * scale;
    }
    __syncthreads();
    if (tid < 32) {
        float* row = &ss[tid * 16];
        float mx = row[0];
        #pragma unroll
        for (int i = 1; i < 16; i++) mx = fmaxf(mx, row[i]);
        float sum = 0.f;
        #pragma unroll
        for (int i = 0; i < 16; i++) { row[i] = expf(row[i] - mx); sum += row[i]; }
        float inv = 1.f / sum;
        #pragma unroll
        for (int i = 0; i < 16; i++) row[i] *= inv;
    }
    __syncthreads();
    int c = tid;
    int h = c >> 7;
    float vv[16];
    #pragma unroll
    for (int m = 0; m < 16; m++)
        vv[m] = g_kv[((m << 10) + p) * 512 + 256 + c];
    #pragma unroll
    for (int l = 0; l < 16; l++) {
        const float* ar = &ss[h * 256 + l * 16];
        float a = 0.f;
        #pragma unroll
        for (int m = 0; m < 16; m++) a += ar[m] * vv[m];
        g_o[((l << 10) + p) * 256 + c] = a;
    }
}

// conditional transposed write-back: feat[n,c,y,x] = fea2[n, p, c] if active
__global__ void k_writeback(const int* __restrict__ words, int s) {
    if (words[s] == 0) return;       // words[0, s]
    __shared__ float tile[32][33];
    int n = blockIdx.x, c0 = blockIdx.y * 32, p0 = blockIdx.z * 32;
    int tid = threadIdx.x;
    int cc = tid & 31, pr = tid >> 5;
    #pragma unroll
    for (int i = 0; i < 4; i++) {
        int pp = i * 8 + pr;
        tile[pp][cc] = g_fea2[(n * 1024 + p0 + pp) * 256 + c0 + cc];
    }
    __syncthreads();
    #pragma unroll
    for (int i = 0; i < 4; i++) {
        int crow = i * 8 + pr;
        g_feat[n * (VD * PPOS) + (c0 + crow) * 1024 + p0 + cc] = tile[cc][crow];
    }
}

// ---------------- launch ------------------------------------------------------

extern "C" void kernel_launch(void* const* d_in, const int* in_sizes, int n_in,
                              void* d_out, int out_size) {
    (void)in_sizes; (void)n_in; (void)out_size;
    const float* hn        = (const float*)d_in[1];
    const float* feature   = (const float*)d_in[2];
    const float* embedding = (const float*)d_in[3];
    const int*   words     = (const int*)  d_in[4];
    const float* qconv_w   = (const float*)d_in[5];
    const float* qconv_b   = (const float*)d_in[6];
    const float* mconv_w   = (const float*)d_in[7];
    const float* mnorm_g   = (const float*)d_in[8];
    const float* mnorm_b   = (const float*)d_in[9];
    const float* in_proj_w = (const float*)d_in[10];
    const float* in_proj_b = (const float*)d_in[11];
    const float* out_proj_w= (const float*)d_in[12];
    const float* out_proj_b= (const float*)d_in[13];
    const float* norm_g    = (const float*)d_in[14];
    const float* norm_b    = (const float*)d_in[15];
    const float* lin1_w    = (const float*)d_in[16];
    const float* lin1_b    = (const float*)d_in[17];
    const float* lin2_w    = (const float*)d_in[18];
    const float* lin2_b    = (const float*)d_in[19];
    const float* normf_g   = (const float*)d_in[20];
    const float* normf_b   = (const float*)d_in[21];

    float *p_WkvT, *p_WoT, *p_W1T, *p_W2T;
    float *p_t, *p_tn, *p_kv, *p_o, *p_u, *p_fea, *p_f1, *p_u2, *p_fea2;
    cudaGetSymbolAddress((void**)&p_WkvT, g_WkvT);
    cudaGetSymbolAddress((void**)&p_WoT,  g_WoT);
    cudaGetSymbolAddress((void**)&p_W1T,  g_W1T);
    cudaGetSymbolAddress((void**)&p_W2T,  g_W2T);
    cudaGetSymbolAddress((void**)&p_t,    g_t);
    cudaGetSymbolAddress((void**)&p_tn,   g_tn);
    cudaGetSymbolAddress((void**)&p_kv,   g_kv);
    cudaGetSymbolAddress((void**)&p_o,    g_o);
    cudaGetSymbolAddress((void**)&p_u,    g_u);
    cudaGetSymbolAddress((void**)&p_fea,  g_fea);
    cudaGetSymbolAddress((void**)&p_f1,   g_f1);
    cudaGetSymbolAddress((void**)&p_u2,   g_u2);
    cudaGetSymbolAddress((void**)&p_fea2, g_fea2);

    // ---- prep (per launch, deterministic) ----
    k_copy_feat<<<4096, 256>>>((const float4*)feature);
    k_wr <<<(9 * VD * VD + 255) / 256, 256>>>(mconv_w);
    k_whs<<<(9 * VD * HND + 255) / 256, 256>>>(mconv_w);
    k_transpose<<<(512 * 256 + 255) / 256, 256>>>(p_WkvT, in_proj_w + 256 * 256, 512);
    k_transpose<<<(256 * 256 + 255) / 256, 256>>>(p_WoT, out_proj_w, 256);
    k_transpose<<<(256 * 256 + 255) / 256, 256>>>(p_W1T, lin1_w, 256);
    k_transpose<<<(256 * 256 + 255) / 256, 256>>>(p_W2T, lin2_w, 256);
    k_hnp  <<<(NB * VD * 9 + 255) / 256, 256>>>(hn);
    k_spart<<<(VD * PPOS + 255) / 256, 256>>>(mconv_w);
    k_base <<<MR * VD / 256, 256>>>();

    // ---- 20 recurrent steps ----
    for (int s = 0; s < SEQL; s++) {
        k_qh<<<NB, 256>>>(embedding, qconv_w, qconv_b, in_proj_w, in_proj_b, s);
        k_conv<<<dim3(128, 2), 256>>>();
        k_ln<<<MR, 256>>>(p_t, p_tn, mnorm_g, mnorm_b);
        k_gemm<512, false, false><<<dim3(128, 4), 256>>>(p_tn, p_WkvT, in_proj_b + 256, nullptr, p_kv);
        k_attn<<<PPOS, 256>>>();
        k_gemm<256, false, true><<<dim3(128, 2), 256>>>(p_o, p_WoT, out_proj_b, p_tn, p_u);
        k_ln<<<MR, 256>>>(p_u, p_fea, norm_g, norm_b);
        k_gemm<256, true, false><<<dim3(128, 2), 256>>>(p_fea, p_W1T, lin1_b, nullptr, p_f1);
        k_gemm<256, false, true><<<dim3(128, 2), 256>>>(p_f1, p_W2T, lin2_b, p_fea, p_u2);
        k_ln<<<MR, 256>>>(p_u2, p_fea2, normf_g, normf_b);
        k_writeback<<<dim3(16, 8, 32), 256>>>(words, s);
    }

    k_copyout<<<4096, 256>>>((float4*)d_out);
}

// round 4
// speedup vs baseline: 1.9424x; 1.9416x over previous
#include <cuda_runtime.h>
#include <cuda_bf16.h>
#include <stdint.h>

#define NB 16
#define SEQL 20
#define HND 512
#define EMBD 300
#define VD 256
#define PPOS 1024
#define MR (NB*PPOS)
#define QROWS 1156   // 34*34

// ---------------- device scratch ---------------------------------------------
__device__ __align__(16) float g_base[MR*VD];
__device__ __align__(16) float g_spart[VD*PPOS];
__device__ __align__(16) float g_whs[9*VD*HND];
__device__ __align__(16) float g_hnp[NB*VD*9];
__device__ __align__(16) float g_qh[NB*VD];
__device__ __align__(16) float g_fpc[MR*VD];
__device__ __align__(16) float g_t[MR*VD];
__device__ __align__(16) float g_tn[MR*VD];
__device__ __align__(16) float g_fea[MR*VD];
__device__ __align__(16) float g_u[MR*VD];
__device__ __align__(16) float g_u2[MR*VD];
__device__ __align__(16) float g_kv[MR*2*VD];
__device__ __align__(16) __nv_bfloat16 g_fbh[NB*QROWS*VD], g_fbl[NB*QROWS*VD];
__device__ __align__(16) __nv_bfloat16 g_tnh[MR*VD],  g_tnl[MR*VD];
__device__ __align__(16) __nv_bfloat16 g_feah[MR*VD], g_feal[MR*VD];
__device__ __align__(16) __nv_bfloat16 g_f1h[MR*VD],  g_f1l[MR*VD];
__device__ __align__(16) __nv_bfloat16 g_oh[MR*VD],   g_ol[MR*VD];
__device__ __align__(16) __nv_bfloat16 g_Wcbh[9*VD*VD], g_Wcbl[9*VD*VD]; // [tap][co][ci]
__device__ __align__(16) __nv_bfloat16 g_Wkvh[2*VD*VD], g_Wkvl[2*VD*VD];
__device__ __align__(16) __nv_bfloat16 g_Woh[VD*VD],  g_Wol[VD*VD];
__device__ __align__(16) __nv_bfloat16 g_W1h[VD*VD],  g_W1l[VD*VD];
__device__ __align__(16) __nv_bfloat16 g_W2h[VD*VD],  g_W2l[VD*VD];

// ---------------- helpers -----------------------------------------------------
__device__ __forceinline__ uint32_t smem_u32(const void* p){
    uint32_t a;
    asm("{ .reg .u64 t; cvta.to.shared.u64 t, %1; cvt.u32.u64 %0, t; }":"=r"(a):"l"(p));
    return a;
}
#define LDSM4(r, addr) asm volatile( \
    "ldmatrix.sync.aligned.m8n8.x4.shared.b16 {%0,%1,%2,%3}, [%4];" \
    : "=r"((r)[0]),"=r"((r)[1]),"=r"((r)[2]),"=r"((r)[3]) : "r"(addr))
#define MMA16816(d, a, b0v, b1v) asm volatile( \
    "mma.sync.aligned.m16n8k16.row.col.f32.bf16.bf16.f32 " \
    "{%0,%1,%2,%3},{%4,%5,%6,%7},{%8,%9},{%0,%1,%2,%3};" \
    : "+f"((d)[0]),"+f"((d)[1]),"+f"((d)[2]),"+f"((d)[3]) \
    : "r"((a)[0]),"r"((a)[1]),"r"((a)[2]),"r"((a)[3]), "r"(b0v),"r"(b1v))

__device__ __forceinline__ void split2(float a, float b, __nv_bfloat16* h, __nv_bfloat16* l, long i){
    __nv_bfloat16 ha=__float2bfloat16(a), hb=__float2bfloat16(b);
    __nv_bfloat162 hv; hv.x=ha; hv.y=hb;
    __nv_bfloat162 lv;
    lv.x=__float2bfloat16(a-__bfloat162float(ha));
    lv.y=__float2bfloat16(b-__bfloat162float(hb));
    *(__nv_bfloat162*)(h+i)=hv; *(__nv_bfloat162*)(l+i)=lv;
}

// ---------------- HMMA GEMM ---------------------------------------------------
// C[M,N] = A[M,K] @ B[N,K]^T via 3-term bf16 split, f32 accum.
// CONV: A is padded 34x34 image, K=2304 (9 taps x 256), B = [tap][co][ci].
// EP: 0 = +bias -> C32            1 = +bias + res -> C32
//     2 = relu(+bias) -> Ch/Cl    3 = relu(+res(base)) -> C32
template<bool CONV, int EP>
__global__ void __launch_bounds__(256) k_hmma(
    const __nv_bfloat16* __restrict__ Ah, const __nv_bfloat16* __restrict__ Al,
    const __nv_bfloat16* __restrict__ Bh, const __nv_bfloat16* __restrict__ Bl,
    float* __restrict__ C32, __nv_bfloat16* __restrict__ Ch, __nv_bfloat16* __restrict__ Cl,
    const float* __restrict__ bias, const float* __restrict__ res, int ldC)
{
    __shared__ __nv_bfloat16 sAh[128*40], sAl[128*40], sBh[128*40], sBl[128*40];
    int tid=threadIdx.x, lane=tid&31, w=tid>>5;
    int m0 = blockIdx.x*128, n0 = blockIdx.y*128;
    int wm = w>>1, wn = w&1;
    float acc[2][8][4];
    #pragma unroll
    for (int i=0;i<2;i++)
        #pragma unroll
        for (int j=0;j<8;j++)
            #pragma unroll
            for (int q=0;q<4;q++) acc[i][j][q]=0.f;
    int nbase=0, p0=0;
    if (CONV){ nbase=(m0>>10)*QROWS; p0=m0&1023; }
    uint32_t bAh=smem_u32(sAh), bAl=smem_u32(sAl), bBh=smem_u32(sBh), bBl=smem_u32(sBl);
    const int NCH = CONV ? 72 : 8;
    for (int kc=0; kc<NCH; kc++){
        int tap=0, k0, tapoff=0;
        if (CONV){ tap=kc>>3; k0=(kc&7)*32; tapoff=(tap/3-1)*34+(tap%3-1); }
        else k0=kc*32;
        __syncthreads();
        #pragma unroll
        for (int i=0;i<2;i++){
            int u=i*256+tid, r=u>>2, c8=(u&3)*8;
            long arow;
            if (CONV){ int p=p0+r; arow=(long)nbase+((p>>5)+1)*34+(p&31)+1+tapoff; }
            else arow=m0+r;
            long brow = CONV ? ((long)tap*256 + n0 + r) : (long)(n0 + r);
            int so = r*40 + c8;
            *(uint4*)(sAh+so) = *(const uint4*)(Ah + arow*256 + k0 + c8);
            *(uint4*)(sAl+so) = *(const uint4*)(Al + arow*256 + k0 + c8);
            *(uint4*)(sBh+so) = *(const uint4*)(Bh + brow*256 + k0 + c8);
            *(uint4*)(sBl+so) = *(const uint4*)(Bl + brow*256 + k0 + c8);
        }
        __syncthreads();
        #pragma unroll
        for (int kk=0; kk<2; kk++){
            uint32_t ah[2][4], al[2][4], bh[4][4], bl[4][4];
            int kcol = kk*16 + (lane>>4)*8;
            #pragma unroll
            for (int mt=0;mt<2;mt++){
                int rr = wm*32 + mt*16 + (lane&15);
                LDSM4(ah[mt], bAh + (rr*40+kcol)*2);
                LDSM4(al[mt], bAl + (rr*40+kcol)*2);
            }
            #pragma unroll
            for (int nt=0;nt<4;nt++){
                int rr = wn*64 + nt*16 + (lane&15);
                LDSM4(bh[nt], bBh + (rr*40+kcol)*2);
                LDSM4(bl[nt], bBl + (rr*40+kcol)*2);
            }
            #pragma unroll
            for (int mt=0;mt<2;mt++)
                #pragma unroll
                for (int nt=0;nt<4;nt++){
                    MMA16816(acc[mt][nt*2],   ah[mt], bh[nt][0], bh[nt][2]);
                    MMA16816(acc[mt][nt*2],   ah[mt], bl[nt][0], bl[nt][2]);
                    MMA16816(acc[mt][nt*2],   al[mt], bh[nt][0], bh[nt][2]);
                    MMA16816(acc[mt][nt*2+1], ah[mt], bh[nt][1], bh[nt][3]);
                    MMA16816(acc[mt][nt*2+1], ah[mt], bl[nt][1], bl[nt][3]);
                    MMA16816(acc[mt][nt*2+1], al[mt], bh[nt][1], bh[nt][3]);
                }
        }
    }
    // epilogue
    int colbase = n0 + wn*64;
    #pragma unroll
    for (int mt=0;mt<2;mt++){
        #pragma unroll
        for (int half=0; half<2; half++){
            long m = m0 + wm*32 + mt*16 + (lane>>2) + half*8;
            #pragma unroll
            for (int nt=0;nt<8;nt++){
                int c = colbase + nt*8 + (lane&3)*2;
                float v0 = acc[mt][nt][half*2+0];
                float v1 = acc[mt][nt][half*2+1];
                if (EP==3){
                    v0 = fmaxf(v0 + res[m*ldC+c],   0.f);
                    v1 = fmaxf(v1 + res[m*ldC+c+1], 0.f);
                    *(float2*)(C32 + m*ldC + c) = make_float2(v0,v1);
                } else if (EP==0){
                    *(float2*)(C32 + m*ldC + c) =
                        make_float2(v0 + bias[c], v1 + bias[c+1]);
                } else if (EP==1){
                    *(float2*)(C32 + m*ldC + c) =
                        make_float2(v0 + bias[c] + res[m*ldC+c],
                                    v1 + bias[c+1] + res[m*ldC+c+1]);
                } else {
                    split2(fmaxf(v0+bias[c],0.f), fmaxf(v1+bias[c+1],0.f),
                           Ch, Cl, m*ldC + c);
                }
            }
        }
    }
}

// ---------------- LayerNorm kernels ------------------------------------------
__global__ void k_ln_split(const float* __restrict__ in, float* __restrict__ out,
                           __nv_bfloat16* __restrict__ oh, __nv_bfloat16* __restrict__ ol,
                           const float* __restrict__ g, const float* __restrict__ b){
    long row = blockIdx.x; int tid = threadIdx.x;
    float x = in[row*256 + tid];
    float s1=x, s2=x*x;
    #pragma unroll
    for (int o=16;o>0;o>>=1){
        s1 += __shfl_xor_sync(0xffffffffu, s1, o);
        s2 += __shfl_xor_sync(0xffffffffu, s2, o);
    }
    __shared__ float w1[8], w2[8];
    if ((tid&31)==0){ w1[tid>>5]=s1; w2[tid>>5]=s2; }
    __syncthreads();
    float t1=0.f,t2=0.f;
    #pragma unroll
    for (int i=0;i<8;i++){ t1+=w1[i]; t2+=w2[i]; }
    float mean = t1*(1.f/256.f);
    float var  = t2*(1.f/256.f) - mean*mean;
    float rr = rsqrtf(var + 1e-5f);
    float y = (x-mean)*rr*g[tid] + b[tid];
    out[row*256+tid] = y;
    __nv_bfloat16 hh = __float2bfloat16(y);
    oh[row*256+tid] = hh;
    ol[row*256+tid] = __float2bfloat16(y - __bfloat162float(hh));
}

__global__ void k_ln_wb(const float* __restrict__ in, const float* __restrict__ g,
                        const float* __restrict__ b, const int* __restrict__ words, int s){
    if (words[s] == 0) return;
    long row = blockIdx.x; int tid = threadIdx.x;
    float x = in[row*256 + tid];
    float s1=x, s2=x*x;
    #pragma unroll
    for (int o=16;o>0;o>>=1){
        s1 += __shfl_xor_sync(0xffffffffu, s1, o);
        s2 += __shfl_xor_sync(0xffffffffu, s2, o);
    }
    __shared__ float w1[8], w2[8];
    if ((tid&31)==0){ w1[tid>>5]=s1; w2[tid>>5]=s2; }
    __syncthreads();
    float t1=0.f,t2=0.f;
    #pragma unroll
    for (int i=0;i<8;i++){ t1+=w1[i]; t2+=w2[i]; }
    float mean = t1*(1.f/256.f);
    float var  = t2*(1.f/256.f) - mean*mean;
    float rr = rsqrtf(var + 1e-5f);
    float y = (x-mean)*rr*g[tid] + b[tid];
    long n = row>>10, p = row&1023;
    long q = ((p>>5)+1)*34 + (p&31) + 1;
    g_fpc[row*256+tid] = y;
    __nv_bfloat16 hh = __float2bfloat16(y);
    g_fbh[(n*QROWS+q)*256+tid] = hh;
    g_fbl[(n*QROWS+q)*256+tid] = __float2bfloat16(y - __bfloat162float(hh));
}

// ---------------- prep / small kernels ---------------------------------------
__global__ void k_zero4(uint4* p, int cnt4){
    int i = blockIdx.x*256 + threadIdx.x;
    if (i < cnt4) p[i] = make_uint4(0,0,0,0);
}
__global__ void k_init(const float* __restrict__ feature){
    __shared__ float tile[32][33];
    int n=blockIdx.x, c0=blockIdx.y*32, p0=blockIdx.z*32;
    int tid=threadIdx.x, cc=tid&31, rr=tid>>5;
    #pragma unroll
    for (int i=0;i<4;i++){
        int cl=i*8+rr;
        tile[cl][cc] = feature[((long)n*256 + c0+cl)*1024 + p0+cc];
    }
    __syncthreads();
    #pragma unroll
    for (int i=0;i<4;i++){
        int pl=i*8+rr; int p=p0+pl; int c=c0+cc;
        float v = tile[cc][pl];
        g_fpc[((long)n*1024+p)*256 + c] = v;
        long q = ((p>>5)+1)*34 + (p&31) + 1;
        __nv_bfloat16 hh = __float2bfloat16(v);
        g_fbh[((long)n*QROWS+q)*256+c] = hh;
        g_fbl[((long)n*QROWS+q)*256+c] = __float2bfloat16(v-__bfloat162float(hh));
    }
}
__global__ void k_copyout(float* __restrict__ out){
    __shared__ float tile[32][33];
    int n=blockIdx.x, c0=blockIdx.y*32, p0=blockIdx.z*32;
    int tid=threadIdx.x, cc=tid&31, rr=tid>>5;
    #pragma unroll
    for (int i=0;i<4;i++){
        int pl=i*8+rr;
        tile[pl][cc] = g_fpc[((long)n*1024 + p0+pl)*256 + c0+cc];
    }
    __syncthreads();
    #pragma unroll
    for (int i=0;i<4;i++){
        int cl=i*8+rr;
        out[((long)n*256 + c0+cl)*1024 + p0+cc] = tile[cc][cl];
    }
}
__global__ void k_split_convw(const float* __restrict__ W){
    int idx = blockIdx.x*256 + threadIdx.x;     // tap*65536 + co*256 + ci
    if (idx >= 9*VD*VD) return;
    int ci = idx&255, co = (idx>>8)&255, tap = idx>>16;
    float v = W[((long)co*776 + ci)*9 + tap];
    __nv_bfloat16 hh = __float2bfloat16(v);
    g_Wcbh[idx] = hh;
    g_Wcbl[idx] = __float2bfloat16(v - __bfloat162float(hh));
}
__global__ void k_splitw(__nv_bfloat16* h, __nv_bfloat16* l, const float* __restrict__ src, int cnt){
    int i = blockIdx.x*256 + threadIdx.x;
    if (i >= cnt) return;
    float v = src[i];
    __nv_bfloat16 hh = __float2bfloat16(v);
    h[i] = hh;
    l[i] = __float2bfloat16(v - __bfloat162float(hh));
}
__global__ void k_whs(const float* __restrict__ W){
    int idx = blockIdx.x*256 + threadIdx.x;
    if (idx >= 9*VD*HND) return;
    int c = idx&511, co = (idx>>9)&255, t = idx>>17;
    int ry=t/3, rx=t%3; float s=0.f;
    const float* w = &W[((long)co*776 + 264 + c)*9];
    #pragma unroll
    for (int ky=0;ky<3;ky++){
        if ((ry==0&&ky==0)||(ry==2&&ky==2)) continue;
        #pragma unroll
        for (int kx=0;kx<3;kx++){
            if ((rx==0&&kx==0)||(rx==2&&kx==2)) continue;
            s += w[ky*3+kx];
        }
    }
    g_whs[idx] = s;
}
__global__ void k_hnp(const float* __restrict__ hn){
    int idx = blockIdx.x*256 + threadIdx.x;
    if (idx >= NB*VD*9) return;
    int t = idx%9, co = (idx/9)%256, n = idx/(9*256);
    const float* h = &hn[n*HND];
    const float* w = &g_whs[((long)t*256+co)*HND];
    float s=0.f;
    for (int c=0;c<HND;c++) s += h[c]*w[c];
    g_hnp[idx] = s;
}
__global__ void k_spart(const float* __restrict__ W){
    int idx = blockIdx.x*256 + threadIdx.x;
    if (idx >= VD*PPOS) return;
    int p = idx&1023, co = idx>>10;
    int y = p>>5, x = p&31; float s=0.f;
    #pragma unroll
    for (int ky=0;ky<3;ky++){
        int yy=y+ky-1; if (yy<0||yy>31) continue;
        #pragma unroll
        for (int kx=0;kx<3;kx++){
            int xx=x+kx-1; if (xx<0||xx>31) continue;
            const float* w = &W[((long)co*776+256)*9 + ky*3+kx];
            float fx=(float)xx, fy=(float)yy;
            float xmin=fx*0.0625f-1.f, xmax=(fx+1.f)*0.0625f-1.f;
            float ymin=fy*0.0625f-1.f, ymax=(fy+1.f)*0.0625f-1.f;
            s += w[0]*xmin + w[9]*ymin + w[18]*xmax + w[27]*ymax
               + w[36]*(0.5f*(xmin+xmax)) + w[45]*(0.5f*(ymin+ymax))
               + w[54]*0.03125f + w[63]*0.03125f;
        }
    }
    g_spart[idx] = s;
}
__global__ void k_base(){
    int idx = blockIdx.x*256 + threadIdx.x;
    int co = idx&255, m = idx>>8;
    int n=m>>10, p=m&1023, y=p>>5, x=p&31;
    int ry=(y==0)?0:((y==31)?2:1);
    int rx=(x==0)?0:((x==31)?2:1);
    g_base[idx] = g_spart[co*1024+p] + g_hnp[((long)n*256+co)*9 + ry*3+rx];
}
__global__ void k_qh(const float* __restrict__ emb, const float* __restrict__ qw,
                     const float* __restrict__ qb, const float* __restrict__ ipw,
                     const float* __restrict__ ipb, int s){
    __shared__ float qs[VD];
    int n = blockIdx.x, v = threadIdx.x;
    const float* e = emb + ((long)n*SEQL + s)*EMBD;
    float a = qb[v];
    const float* wr = &qw[(long)v*EMBD];
    for (int i=0;i<EMBD;i++) a += e[i]*wr[i];
    qs[v] = fmaxf(a, 0.f);
    __syncthreads();
    float a2 = ipb[v];
    const float* wq = &ipw[(long)v*VD];
    for (int c=0;c<VD;c++) a2 += qs[c]*wq[c];
    g_qh[n*VD+v] = a2;
}
__global__ void k_attn(){
    __shared__ float khs[16*257];
    __shared__ float qs[16*257];
    __shared__ float ss[512];
    int p = blockIdx.x, tid = threadIdx.x;
    #pragma unroll
    for (int m=0;m<16;m++) khs[m*257+tid] = g_kv[(((long)m<<10)+p)*512 + tid];
    #pragma unroll
    for (int l=0;l<16;l++) qs[l*257+tid] = g_qh[l*256+tid];
    __syncthreads();
    const float scale = 0.08838834764831845f;
    #pragma unroll
    for (int it=0;it<2;it++){
        int idx = it*256+tid;
        int h=idx>>8, l=(idx>>4)&15, m=idx&15;
        const float* qv=&qs[l*257+h*128];
        const float* kv=&khs[m*257+h*128];
        float a=0.f;
        #pragma unroll 8
        for (int d=0;d<128;d++) a += qv[d]*kv[d];
        ss[idx] = a*scale;
    }
    __syncthreads();
    if (tid < 32){
        float* row = &ss[tid*16];
        float mx = row[0];
        #pragma unroll
        for (int i=1;i<16;i++) mx = fmaxf(mx,row[i]);
        float sum=0.f;
        #pragma unroll
        for (int i=0;i<16;i++){ row[i]=expf(row[i]-mx); sum+=row[i]; }
        float inv=1.f/sum;
        #pragma unroll
        for (int i=0;i<16;i++) row[i]*=inv;
    }
    __syncthreads();
    int c = tid, h = c>>7;
    float vv[16];
    #pragma unroll
    for (int m=0;m<16;m++) vv[m] = g_kv[(((long)m<<10)+p)*512 + 256 + c];
    #pragma unroll
    for (int l=0;l<16;l++){
        const float* ar = &ss[h*256 + l*16];
        float a=0.f;
        #pragma unroll
        for (int m=0;m<16;m++) a += ar[m]*vv[m];
        long o = (((long)l<<10)+p)*256 + c;
        __nv_bfloat16 hh = __float2bfloat16(a);
        g_oh[o] = hh;
        g_ol[o] = __float2bfloat16(a - __bfloat162float(hh));
    }
}

// ---------------- launch ------------------------------------------------------
extern "C" void kernel_launch(void* const* d_in, const int* in_sizes, int n_in,
                              void* d_out, int out_size) {
    (void)in_sizes; (void)n_in; (void)out_size;
    const float* hn        = (const float*)d_in[1];
    const float* feature   = (const float*)d_in[2];
    const float* embedding = (const float*)d_in[3];
    const int*   words     = (const int*)  d_in[4];
    const float* qconv_w   = (const float*)d_in[5];
    const float* qconv_b   = (const float*)d_in[6];
    const float* mconv_w   = (const float*)d_in[7];
    const float* mnorm_g   = (const float*)d_in[8];
    const float* mnorm_b   = (const float*)d_in[9];
    const float* in_proj_w = (const float*)d_in[10];
    const float* in_proj_b = (const float*)d_in[11];
    const float* out_proj_w= (const float*)d_in[12];
    const float* out_proj_b= (const float*)d_in[13];
    const float* norm_g    = (const float*)d_in[14];
    const float* norm_b    = (const float*)d_in[15];
    const float* lin1_w    = (const float*)d_in[16];
    const float* lin1_b    = (const float*)d_in[17];
    const float* lin2_w    = (const float*)d_in[18];
    const float* lin2_b    = (const float*)d_in[19];
    const float* normf_g   = (const float*)d_in[20];
    const float* normf_b   = (const float*)d_in[21];

    __nv_bfloat16 *p_fbh,*p_fbl,*p_tnh,*p_tnl,*p_feah,*p_feal,*p_f1h,*p_f1l,*p_oh,*p_ol;
    __nv_bfloat16 *p_Wcbh,*p_Wcbl,*p_Wkvh,*p_Wkvl,*p_Woh,*p_Wol,*p_W1h,*p_W1l,*p_W2h,*p_W2l;
    float *p_t,*p_tn,*p_fea,*p_u,*p_u2,*p_kv,*p_base;
    cudaGetSymbolAddress((void**)&p_fbh, g_fbh);   cudaGetSymbolAddress((void**)&p_fbl, g_fbl);
    cudaGetSymbolAddress((void**)&p_tnh, g_tnh);   cudaGetSymbolAddress((void**)&p_tnl, g_tnl);
    cudaGetSymbolAddress((void**)&p_feah, g_feah); cudaGetSymbolAddress((void**)&p_feal, g_feal);
    cudaGetSymbolAddress((void**)&p_f1h, g_f1h);   cudaGetSymbolAddress((void**)&p_f1l, g_f1l);
    cudaGetSymbolAddress((void**)&p_oh, g_oh);     cudaGetSymbolAddress((void**)&p_ol, g_ol);
    cudaGetSymbolAddress((void**)&p_Wcbh, g_Wcbh); cudaGetSymbolAddress((void**)&p_Wcbl, g_Wcbl);
    cudaGetSymbolAddress((void**)&p_Wkvh, g_Wkvh); cudaGetSymbolAddress((void**)&p_Wkvl, g_Wkvl);
    cudaGetSymbolAddress((void**)&p_Woh, g_Woh);   cudaGetSymbolAddress((void**)&p_Wol, g_Wol);
    cudaGetSymbolAddress((void**)&p_W1h, g_W1h);   cudaGetSymbolAddress((void**)&p_W1l, g_W1l);
    cudaGetSymbolAddress((void**)&p_W2h, g_W2h);   cudaGetSymbolAddress((void**)&p_W2l, g_W2l);
    cudaGetSymbolAddress((void**)&p_t,   g_t);     cudaGetSymbolAddress((void**)&p_tn,  g_tn);
    cudaGetSymbolAddress((void**)&p_fea, g_fea);   cudaGetSymbolAddress((void**)&p_u,   g_u);
    cudaGetSymbolAddress((void**)&p_u2,  g_u2);    cudaGetSymbolAddress((void**)&p_kv,  g_kv);
    cudaGetSymbolAddress((void**)&p_base,g_base);

    // prep
    int zc = (NB*QROWS*VD*2)/16;
    k_zero4<<<(zc+255)/256, 256>>>((uint4*)p_fbh, zc);
    k_zero4<<<(zc+255)/256, 256>>>((uint4*)p_fbl, zc);
    k_init<<<dim3(16,8,32), 256>>>(feature);
    k_split_convw<<<(9*VD*VD+255)/256, 256>>>(mconv_w);
    k_splitw<<<(2*VD*VD+255)/256, 256>>>(p_Wkvh, p_Wkvl, in_proj_w + VD*VD, 2*VD*VD);
    k_splitw<<<(VD*VD+255)/256, 256>>>(p_Woh, p_Wol, out_proj_w, VD*VD);
    k_splitw<<<(VD*VD+255)/256, 256>>>(p_W1h, p_W1l, lin1_w, VD*VD);
    k_splitw<<<(VD*VD+255)/256, 256>>>(p_W2h, p_W2l, lin2_w, VD*VD);
    k_whs<<<(9*VD*HND+255)/256, 256>>>(mconv_w);
    k_hnp<<<(NB*VD*9+255)/256, 256>>>(hn);
    k_spart<<<(VD*PPOS+255)/256, 256>>>(mconv_w);
    k_base<<<MR*VD/256, 256>>>();

    for (int s=0; s<SEQL; s++){
        k_qh<<<NB, 256>>>(embedding, qconv_w, qconv_b, in_proj_w, in_proj_b, s);
        k_hmma<true,3><<<dim3(128,2), 256>>>(p_fbh, p_fbl, p_Wcbh, p_Wcbl,
            p_t, nullptr, nullptr, nullptr, p_base, 256);
        k_ln_split<<<MR, 256>>>(p_t, p_tn, p_tnh, p_tnl, mnorm_g, mnorm_b);
        k_hmma<false,0><<<dim3(128,4), 256>>>(p_tnh, p_tnl, p_Wkvh, p_Wkvl,
            p_kv, nullptr, nullptr, in_proj_b + VD, nullptr, 512);
        k_attn<<<PPOS, 256>>>();
        k_hmma<false,1><<<dim3(128,2), 256>>>(p_oh, p_ol, p_Woh, p_Wol,
            p_u, nullptr, nullptr, out_proj_b, p_tn, 256);
        k_ln_split<<<MR, 256>>>(p_u, p_fea, p_feah, p_feal, norm_g, norm_b);
        k_hmma<false,2><<<dim3(128,2), 256>>>(p_feah, p_feal, p_W1h, p_W1l,
            nullptr, p_f1h, p_f1l, lin1_b, nullptr, 256);
        k_hmma<false,1><<<dim3(128,2), 256>>>(p_f1h, p_f1l, p_W2h, p_W2l,
            p_u2, nullptr, nullptr, lin2_b, p_fea, 256);
        k_ln_wb<<<MR, 256>>>(p_u2, normf_g, normf_b, words, s);
    }
    k_copyout<<<dim3(16,8,32), 256>>>((float*)d_out);
}

// round 7
// speedup vs baseline: 2.2266x; 1.1463x over previous
#include <cuda_runtime.h>
#include <cuda_bf16.h>
#include <stdint.h>

#define NB 16
#define SEQL 20
#define HND 512
#define EMBD 300
#define VD 256
#define PPOS 1024
#define MR (NB*PPOS)
#define QROWS 1156   // 34*34

// ---------------- device scratch ---------------------------------------------
__device__ __align__(16) float g_base[MR*VD];
__device__ __align__(16) float g_spart[VD*PPOS];
__device__ __align__(16) float g_whs[9*VD*HND];
__device__ __align__(16) float g_hnp[NB*VD*9];
__device__ __align__(16) float g_qh[NB*VD];
__device__ __align__(16) float g_fpc[MR*VD];
__device__ __align__(16) float g_tn[MR*VD];
__device__ __align__(16) float g_fea[MR*VD];
__device__ __align__(16) float g_kv[MR*2*VD];
__device__ __align__(16) __nv_bfloat16 g_fbh[NB*QROWS*VD], g_fbl[NB*QROWS*VD];
__device__ __align__(16) __nv_bfloat16 g_tnh[MR*VD],  g_tnl[MR*VD];
__device__ __align__(16) __nv_bfloat16 g_feah[MR*VD], g_feal[MR*VD];
__device__ __align__(16) __nv_bfloat16 g_f1h[MR*VD],  g_f1l[MR*VD];
__device__ __align__(16) __nv_bfloat16 g_oh[MR*VD],   g_ol[MR*VD];
__device__ __align__(16) __nv_bfloat16 g_Wcbh[9*VD*VD], g_Wcbl[9*VD*VD]; // [tap][co][ci]
__device__ __align__(16) __nv_bfloat16 g_Wkvh[2*VD*VD], g_Wkvl[2*VD*VD];
__device__ __align__(16) __nv_bfloat16 g_Woh[VD*VD],  g_Wol[VD*VD];
__device__ __align__(16) __nv_bfloat16 g_W1h[VD*VD],  g_W1l[VD*VD];
__device__ __align__(16) __nv_bfloat16 g_W2h[VD*VD],  g_W2l[VD*VD];

// ---------------- helpers -----------------------------------------------------
__device__ __forceinline__ uint32_t smem_u32(const void* p){
    uint32_t a;
    asm("{ .reg .u64 t; cvta.to.shared.u64 t, %1; cvt.u32.u64 %0, t; }":"=r"(a):"l"(p));
    return a;
}
#define LDSM4(r, addr) asm volatile( \
    "ldmatrix.sync.aligned.m8n8.x4.shared.b16 {%0,%1,%2,%3}, [%4];" \
    : "=r"((r)[0]),"=r"((r)[1]),"=r"((r)[2]),"=r"((r)[3]) : "r"(addr))
#define MMA16816(d, a, b0v, b1v) asm volatile( \
    "mma.sync.aligned.m16n8k16.row.col.f32.bf16.bf16.f32 " \
    "{%0,%1,%2,%3},{%4,%5,%6,%7},{%8,%9},{%0,%1,%2,%3};" \
    : "+f"((d)[0]),"+f"((d)[1]),"+f"((d)[2]),"+f"((d)[3]) \
    : "r"((a)[0]),"r"((a)[1]),"r"((a)[2]),"r"((a)[3]), "r"(b0v),"r"(b1v))
#define CPA16(dst,src) asm volatile("cp.async.cg.shared.global [%0], [%1], 16;"::"r"(dst),"l"(src))
#define CPA_COMMIT()   asm volatile("cp.async.commit_group;" ::: "memory")
#define CPA_WAIT1()    asm volatile("cp.async.wait_group 1;" ::: "memory")

__device__ __forceinline__ void split2(float a, float b, __nv_bfloat16* h, __nv_bfloat16* l, long i){
    __nv_bfloat16 ha=__float2bfloat16(a), hb=__float2bfloat16(b);
    __nv_bfloat162 hv; hv.x=ha; hv.y=hb;
    __nv_bfloat162 lv;
    lv.x=__float2bfloat16(a-__bfloat162float(ha));
    lv.y=__float2bfloat16(b-__bfloat162float(hb));
    *(__nv_bfloat162*)(h+i)=hv; *(__nv_bfloat162*)(l+i)=lv;
}

// stage layout (bytes): AH 0 | AL 10240 | BH 20480 | BL 40960 ; stage=61440
#define OFF_AL 10240
#define OFF_BH 20480
#define OFF_BL 40960
#define STAGE  61440
#define SMEMSZ (3*STAGE)

// MODE 0 conv(+base relu, LN->tn)   1 kv(+bias)    2 out(+bias+res, LN->fea)
// MODE 3 lin1(+bias relu ->split)   4 lin2(+bias+res, LN, gated writeback)
template<int MODE>
__global__ void __launch_bounds__(512,1) k_gm(
    const __nv_bfloat16* __restrict__ Ah, const __nv_bfloat16* __restrict__ Al,
    const __nv_bfloat16* __restrict__ Bh, const __nv_bfloat16* __restrict__ Bl,
    const float* __restrict__ bias, const float* __restrict__ gamma,
    const float* __restrict__ beta, const float* __restrict__ res,
    float* __restrict__ outF, __nv_bfloat16* __restrict__ outH,
    __nv_bfloat16* __restrict__ outL, const int* __restrict__ words, int s)
{
    constexpr bool CONV = (MODE==0);
    constexpr bool HASLN = (MODE==0)||(MODE==2)||(MODE==4);
    extern __shared__ char smem[];
    __shared__ float red1[128][4], red2[128][4];
    uint32_t sb = smem_u32(smem);
    int tid=threadIdx.x, lane=tid&31, w=tid>>5;
    int wm=w>>2, wn=w&3;
    int m0 = blockIdx.x*128;
    int col0 = (MODE==1) ? blockIdx.y*256 : 0;
    int nbase=0, p0=0;
    if (CONV){ nbase=(m0>>10)*QROWS; p0=m0&1023; }
    const int NCH = CONV ? 72 : 8;

    float acc[2][8][4];
    #pragma unroll
    for (int i=0;i<2;i++)
        #pragma unroll
        for (int j=0;j<8;j++)
            #pragma unroll
            for (int q=0;q<4;q++) acc[i][j][q]=0.f;

    // ---- prefetch lambda (macro-ish) ----
    auto prefetch = [&](int stage, uint32_t bufb){
        int tap=0,k0,tapoff=0;
        if (CONV){ tap=stage>>3; k0=(stage&7)*32; tapoff=(tap/3-1)*34+(tap%3-1); }
        else k0=stage*32;
        {   // A: 128 rows x 32 cols, 512 xfers each for h/l
            int r=tid>>2, c8=(tid&3)*8;
            long arow;
            if (CONV){ int p=p0+r; arow=(long)nbase+((p>>5)+1)*34+(p&31)+1+tapoff; }
            else arow=m0+r;
            uint32_t so = bufb + (uint32_t)(r*40+c8)*2;
            CPA16(so,          (const char*)(Ah + arow*256 + k0 + c8));
            CPA16(so + OFF_AL, (const char*)(Al + arow*256 + k0 + c8));
        }
        #pragma unroll
        for (int i=0;i<2;i++){   // B: 256 rows x 32 cols
            int u=i*512+tid, r=u>>2, c8=(u&3)*8;
            long brow = CONV ? ((long)tap*256 + r) : (long)(col0 + r);
            uint32_t so = bufb + (uint32_t)(r*40+c8)*2;
            CPA16(so + OFF_BH, (const char*)(Bh + brow*256 + k0 + c8));
            CPA16(so + OFF_BL, (const char*)(Bl + brow*256 + k0 + c8));
        }
    };

    prefetch(0, sb);          CPA_COMMIT();
    if (NCH>1){ prefetch(1, sb+STAGE); CPA_COMMIT(); }

    for (int kc=0; kc<NCH; kc++){
        CPA_WAIT1();
        __syncthreads();
        if (kc+2 < NCH) prefetch(kc+2, sb + ((kc+2)%3)*STAGE);
        CPA_COMMIT();
        uint32_t bufb = sb + (kc%3)*STAGE;
        #pragma unroll
        for (int kk=0;kk<2;kk++){
            uint32_t ah[2][4], al[2][4];
            int kcol = kk*16 + (lane>>4)*8;
            #pragma unroll
            for (int mt=0;mt<2;mt++){
                int rr = wm*32 + mt*16 + (lane&15);
                LDSM4(ah[mt], bufb + (uint32_t)(rr*40+kcol)*2);
                LDSM4(al[mt], bufb + OFF_AL + (uint32_t)(rr*40+kcol)*2);
            }
            #pragma unroll
            for (int ntp=0;ntp<2;ntp++){
                uint32_t bh[2][4], bl[2][4];
                #pragma unroll
                for (int j=0;j<2;j++){
                    int rr = wn*64 + (ntp*2+j)*16 + (lane&15);
                    LDSM4(bh[j], bufb + OFF_BH + (uint32_t)(rr*40+kcol)*2);
                    LDSM4(bl[j], bufb + OFF_BL + (uint32_t)(rr*40+kcol)*2);
                }
                #pragma unroll
                for (int mt=0;mt<2;mt++)
                    #pragma unroll
                    for (int j=0;j<2;j++){
                        int na = (ntp*2+j)*2;
                        MMA16816(acc[mt][na],   ah[mt], bh[j][0], bh[j][2]);
                        MMA16816(acc[mt][na],   ah[mt], bl[j][0], bl[j][2]);
                        MMA16816(acc[mt][na],   al[mt], bh[j][0], bh[j][2]);
                        MMA16816(acc[mt][na+1], ah[mt], bh[j][1], bh[j][3]);
                        MMA16816(acc[mt][na+1], ah[mt], bl[j][1], bl[j][3]);
                        MMA16816(acc[mt][na+1], al[mt], bh[j][1], bh[j][3]);
                    }
            }
        }
    }
    __syncthreads();

    // ---------------- epilogue ------------------------------------------------
    int colbase = wn*64;
    // pre-transform into acc; accumulate LN sums
    #pragma unroll
    for (int mt=0;mt<2;mt++){
        #pragma unroll
        for (int half=0;half<2;half++){
            int rowL = wm*32 + mt*16 + (lane>>2) + half*8;
            long m = m0 + rowL;
            float s1=0.f, s2=0.f;
            #pragma unroll
            for (int ntq=0;ntq<8;ntq++){
                int c = colbase + ntq*8 + (lane&3)*2;
                float v0 = acc[mt][ntq][half*2+0];
                float v1 = acc[mt][ntq][half*2+1];
                if (MODE==0){
                    v0 = fmaxf(v0 + res[m*256+c],   0.f);
                    v1 = fmaxf(v1 + res[m*256+c+1], 0.f);
                } else if (MODE==1){
                    v0 += bias[col0+c];  v1 += bias[col0+c+1];
                } else if (MODE==2 || MODE==4){
                    v0 += bias[c]   + res[m*256+c];
                    v1 += bias[c+1] + res[m*256+c+1];
                } else {
                    v0 = fmaxf(v0 + bias[c],   0.f);
                    v1 = fmaxf(v1 + bias[c+1], 0.f);
                }
                acc[mt][ntq][half*2+0] = v0;
                acc[mt][ntq][half*2+1] = v1;
                if (HASLN){ s1 += v0+v1; s2 += v0*v0 + v1*v1; }
            }
            if (HASLN){
                s1 += __shfl_xor_sync(0xffffffffu, s1, 1);
                s1 += __shfl_xor_sync(0xffffffffu, s1, 2);
                s2 += __shfl_xor_sync(0xffffffffu, s2, 1);
                s2 += __shfl_xor_sync(0xffffffffu, s2, 2);
                if ((lane&3)==0){ red1[rowL][wn]=s1; red2[rowL][wn]=s2; }
            }
        }
    }
    if (HASLN) __syncthreads();

    bool act = true;
    if (MODE==4) act = (words[s] != 0);

    #pragma unroll
    for (int mt=0;mt<2;mt++){
        #pragma unroll
        for (int half=0;half<2;half++){
            int rowL = wm*32 + mt*16 + (lane>>2) + half*8;
            long m = m0 + rowL;
            float mean=0.f, rstd=0.f;
            if (HASLN){
                float t1 = red1[rowL][0]+red1[rowL][1]+red1[rowL][2]+red1[rowL][3];
                float t2 = red2[rowL][0]+red2[rowL][1]+red2[rowL][2]+red2[rowL][3];
                mean = t1*(1.f/256.f);
                float var = t2*(1.f/256.f) - mean*mean;
                rstd = rsqrtf(var + 1e-5f);
            }
            long n=0,q=0;
            if (MODE==4){
                n = m>>10; long p = m&1023;
                q = ((p>>5)+1)*34 + (p&31) + 1;
            }
            #pragma unroll
            for (int ntq=0;ntq<8;ntq++){
                int c = colbase + ntq*8 + (lane&3)*2;
                float v0 = acc[mt][ntq][half*2+0];
                float v1 = acc[mt][ntq][half*2+1];
                if (MODE==0 || MODE==2){
                    float y0=(v0-mean)*rstd*gamma[c]+beta[c];
                    float y1=(v1-mean)*rstd*gamma[c+1]+beta[c+1];
                    *(float2*)(outF + m*256 + c) = make_float2(y0,y1);
                    split2(y0,y1,outH,outL, m*256+c);
                } else if (MODE==1){
                    *(float2*)(outF + m*512 + col0 + c) = make_float2(v0,v1);
                } else if (MODE==3){
                    split2(v0,v1,outH,outL, m*256+c);
                } else {
                    float y0=(v0-mean)*rstd*gamma[c]+beta[c];
                    float y1=(v1-mean)*rstd*gamma[c+1]+beta[c+1];
                    if (act){
                        *(float2*)(g_fpc + m*256 + c) = make_float2(y0,y1);
                        split2(y0,y1,g_fbh,g_fbl,(n*QROWS+q)*256+c);
                    }
                }
            }
        }
    }
}

// ---------------- prep / small kernels ---------------------------------------
__global__ void k_zero4(uint4* p, int cnt4){
    int i = blockIdx.x*256 + threadIdx.x;
    if (i < cnt4) p[i] = make_uint4(0,0,0,0);
}
__global__ void k_init(const float* __restrict__ feature){
    __shared__ float tile[32][33];
    int n=blockIdx.x, c0=blockIdx.y*32, p0=blockIdx.z*32;
    int tid=threadIdx.x, cc=tid&31, rr=tid>>5;
    #pragma unroll
    for (int i=0;i<4;i++){
        int cl=i*8+rr;
        tile[cl][cc] = feature[((long)n*256 + c0+cl)*1024 + p0+cc];
    }
    __syncthreads();
    #pragma unroll
    for (int i=0;i<4;i++){
        int pl=i*8+rr; int p=p0+pl; int c=c0+cc;
        float v = tile[cc][pl];
        g_fpc[((long)n*1024+p)*256 + c] = v;
        long q = ((p>>5)+1)*34 + (p&31) + 1;
        __nv_bfloat16 hh = __float2bfloat16(v);
        g_fbh[((long)n*QROWS+q)*256+c] = hh;
        g_fbl[((long)n*QROWS+q)*256+c] = __float2bfloat16(v-__bfloat162float(hh));
    }
}
__global__ void k_copyout(float* __restrict__ out){
    __shared__ float tile[32][33];
    int n=blockIdx.x, c0=blockIdx.y*32, p0=blockIdx.z*32;
    int tid=threadIdx.x, cc=tid&31, rr=tid>>5;
    #pragma unroll
    for (int i=0;i<4;i++){
        int pl=i*8+rr;
        tile[pl][cc] = g_fpc[((long)n*1024 + p0+pl)*256 + c0+cc];
    }
    __syncthreads();
    #pragma unroll
    for (int i=0;i<4;i++){
        int cl=i*8+rr;
        out[((long)n*256 + c0+cl)*1024 + p0+cc] = tile[cc][cl];
    }
}
__global__ void k_split_convw(const float* __restrict__ W){
    int idx = blockIdx.x*256 + threadIdx.x;
    if (idx >= 9*VD*VD) return;
    int ci = idx&255, co = (idx>>8)&255, tap = idx>>16;
    float v = W[((long)co*776 + ci)*9 + tap];
    __nv_bfloat16 hh = __float2bfloat16(v);
    g_Wcbh[idx] = hh;
    g_Wcbl[idx] = __float2bfloat16(v - __bfloat162float(hh));
}
__global__ void k_splitw(__nv_bfloat16* h, __nv_bfloat16* l, const float* __restrict__ src, int cnt){
    int i = blockIdx.x*256 + threadIdx.x;
    if (i >= cnt) return;
    float v = src[i];
    __nv_bfloat16 hh = __float2bfloat16(v);
    h[i] = hh;
    l[i] = __float2bfloat16(v - __bfloat162float(hh));
}
__global__ void k_whs(const float* __restrict__ W){
    int idx = blockIdx.x*256 + threadIdx.x;
    if (idx >= 9*VD*HND) return;
    int c = idx&511, co = (idx>>9)&255, t = idx>>17;
    int ry=t/3, rx=t%3; float s=0.f;
    const float* w = &W[((long)co*776 + 264 + c)*9];
    #pragma unroll
    for (int ky=0;ky<3;ky++){
        if ((ry==0&&ky==0)||(ry==2&&ky==2)) continue;
        #pragma unroll
        for (int kx=0;kx<3;kx++){
            if ((rx==0&&kx==0)||(rx==2&&kx==2)) continue;
            s += w[ky*3+kx];
        }
    }
    g_whs[idx] = s;
}
__global__ void k_hnp(const float* __restrict__ hn){
    int idx = blockIdx.x*256 + threadIdx.x;
    if (idx >= NB*VD*9) return;
    int t = idx%9, co = (idx/9)%256, n = idx/(9*256);
    const float* h = &hn[n*HND];
    const float* w = &g_whs[((long)t*256+co)*HND];
    float s=0.f;
    for (int c=0;c<HND;c++) s += h[c]*w[c];
    g_hnp[idx] = s;
}
__global__ void k_spart(const float* __restrict__ W){
    int idx = blockIdx.x*256 + threadIdx.x;
    if (idx >= VD*PPOS) return;
    int p = idx&1023, co = idx>>10;
    int y = p>>5, x = p&31; float s=0.f;
    #pragma unroll
    for (int ky=0;ky<3;ky++){
        int yy=y+ky-1; if (yy<0||yy>31) continue;
        #pragma unroll
        for (int kx=0;kx<3;kx++){
            int xx=x+kx-1; if (xx<0||xx>31) continue;
            const float* w = &W[((long)co*776+256)*9 + ky*3+kx];
            float fx=(float)xx, fy=(float)yy;
            float xmin=fx*0.0625f-1.f, xmax=(fx+1.f)*0.0625f-1.f;
            float ymin=fy*0.0625f-1.f, ymax=(fy+1.f)*0.0625f-1.f;
            s += w[0]*xmin + w[9]*ymin + w[18]*xmax + w[27]*ymax
               + w[36]*(0.5f*(xmin+xmax)) + w[45]*(0.5f*(ymin+ymax))
               + w[54]*0.03125f + w[63]*0.03125f;
        }
    }
    g_spart[idx] = s;
}
__global__ void k_base(){
    int idx = blockIdx.x*256 + threadIdx.x;
    int co = idx&255, m = idx>>8;
    int n=m>>10, p=m&1023, y=p>>5, x=p&31;
    int ry=(y==0)?0:((y==31)?2:1);
    int rx=(x==0)?0:((x==31)?2:1);
    g_base[idx] = g_spart[co*1024+p] + g_hnp[((long)n*256+co)*9 + ry*3+rx];
}
__global__ void k_qh(const float* __restrict__ emb, const float* __restrict__ qw,
                     const float* __restrict__ qb, const float* __restrict__ ipw,
                     const float* __restrict__ ipb, int s){
    __shared__ float qs[VD];
    int n = blockIdx.x, v = threadIdx.x;
    const float* e = emb + ((long)n*SEQL + s)*EMBD;
    float a = qb[v];
    const float* wr = &qw[(long)v*EMBD];
    for (int i=0;i<EMBD;i++) a += e[i]*wr[i];
    qs[v] = fmaxf(a, 0.f);
    __syncthreads();
    float a2 = ipb[v];
    const float* wq = &ipw[(long)v*VD];
    for (int c=0;c<VD;c++) a2 += qs[c]*wq[c];
    g_qh[n*VD+v] = a2;
}
__global__ void k_attn(){
    __shared__ float khs[16*257];
    __shared__ float qs[16*257];
    __shared__ float ss[512];
    int p = blockIdx.x, tid = threadIdx.x;
    #pragma unroll
    for (int m=0;m<16;m++) khs[m*257+tid] = g_kv[(((long)m<<10)+p)*512 + tid];
    #pragma unroll
    for (int l=0;l<16;l++) qs[l*257+tid] = g_qh[l*256+tid];
    __syncthreads();
    const float scale = 0.08838834764831845f;
    #pragma unroll
    for (int it=0;it<2;it++){
        int idx = it*256+tid;
        int h=idx>>8, l=(idx>>4)&15, m=idx&15;
        const float* qv=&qs[l*257+h*128];
        const float* kv=&khs[m*257+h*128];
        float a=0.f;
        #pragma unroll 8
        for (int d=0;d<128;d++) a += qv[d]*kv[d];
        ss[idx] = a*scale;
    }
    __syncthreads();
    if (tid < 32){
        float* row = &ss[tid*16];
        float mx = row[0];
        #pragma unroll
        for (int i=1;i<16;i++) mx = fmaxf(mx,row[i]);
        float sum=0.f;
        #pragma unroll
        for (int i=0;i<16;i++){ row[i]=expf(row[i]-mx); sum+=row[i]; }
        float inv=1.f/sum;
        #pragma unroll
        for (int i=0;i<16;i++) row[i]*=inv;
    }
    __syncthreads();
    int c = tid, h = c>>7;
    float vv[16];
    #pragma unroll
    for (int m=0;m<16;m++) vv[m] = g_kv[(((long)m<<10)+p)*512 + 256 + c];
    #pragma unroll
    for (int l=0;l<16;l++){
        const float* ar = &ss[h*256 + l*16];
        float a=0.f;
        #pragma unroll
        for (int m=0;m<16;m++) a += ar[m]*vv[m];
        long o = (((long)l<<10)+p)*256 + c;
        __nv_bfloat16 hh = __float2bfloat16(a);
        g_oh[o] = hh;
        g_ol[o] = __float2bfloat16(a - __bfloat162float(hh));
    }
}

// ---------------- launch ------------------------------------------------------
extern "C" void kernel_launch(void* const* d_in, const int* in_sizes, int n_in,
                              void* d_out, int out_size) {
    (void)in_sizes; (void)n_in; (void)out_size;
    const float* hn        = (const float*)d_in[1];
    const float* feature   = (const float*)d_in[2];
    const float* embedding = (const float*)d_in[3];
    const int*   words     = (const int*)  d_in[4];
    const float* qconv_w   = (const float*)d_in[5];
    const float* qconv_b   = (const float*)d_in[6];
    const float* mconv_w   = (const float*)d_in[7];
    const float* mnorm_g   = (const float*)d_in[8];
    const float* mnorm_b   = (const float*)d_in[9];
    const float* in_proj_w = (const float*)d_in[10];
    const float* in_proj_b = (const float*)d_in[11];
    const float* out_proj_w= (const float*)d_in[12];
    const float* out_proj_b= (const float*)d_in[13];
    const float* norm_g    = (const float*)d_in[14];
    const float* norm_b    = (const float*)d_in[15];
    const float* lin1_w    = (const float*)d_in[16];
    const float* lin1_b    = (const float*)d_in[17];
    const float* lin2_w    = (const float*)d_in[18];
    const float* lin2_b    = (const float*)d_in[19];
    const float* normf_g   = (const float*)d_in[20];
    const float* normf_b   = (const float*)d_in[21];

    cudaFuncSetAttribute(k_gm<0>, cudaFuncAttributeMaxDynamicSharedMemorySize, SMEMSZ);
    cudaFuncSetAttribute(k_gm<1>, cudaFuncAttributeMaxDynamicSharedMemorySize, SMEMSZ);
    cudaFuncSetAttribute(k_gm<2>, cudaFuncAttributeMaxDynamicSharedMemorySize, SMEMSZ);
    cudaFuncSetAttribute(k_gm<3>, cudaFuncAttributeMaxDynamicSharedMemorySize, SMEMSZ);
    cudaFuncSetAttribute(k_gm<4>, cudaFuncAttributeMaxDynamicSharedMemorySize, SMEMSZ);

    __nv_bfloat16 *p_fbh,*p_fbl,*p_tnh,*p_tnl,*p_feah,*p_feal,*p_f1h,*p_f1l,*p_oh,*p_ol;
    __nv_bfloat16 *p_Wcbh,*p_Wcbl,*p_Wkvh,*p_Wkvl,*p_Woh,*p_Wol,*p_W1h,*p_W1l,*p_W2h,*p_W2l;
    float *p_tn,*p_fea,*p_kv,*p_base;
    cudaGetSymbolAddress((void**)&p_fbh, g_fbh);   cudaGetSymbolAddress((void**)&p_fbl, g_fbl);
    cudaGetSymbolAddress((void**)&p_tnh, g_tnh);   cudaGetSymbolAddress((void**)&p_tnl, g_tnl);
    cudaGetSymbolAddress((void**)&p_feah, g_feah); cudaGetSymbolAddress((void**)&p_feal, g_feal);
    cudaGetSymbolAddress((void**)&p_f1h, g_f1h);   cudaGetSymbolAddress((void**)&p_f1l, g_f1l);
    cudaGetSymbolAddress((void**)&p_oh, g_oh);     cudaGetSymbolAddress((void**)&p_ol, g_ol);
    cudaGetSymbolAddress((void**)&p_Wcbh, g_Wcbh); cudaGetSymbolAddress((void**)&p_Wcbl, g_Wcbl);
    cudaGetSymbolAddress((void**)&p_Wkvh, g_Wkvh); cudaGetSymbolAddress((void**)&p_Wkvl, g_Wkvl);
    cudaGetSymbolAddress((void**)&p_Woh, g_Woh);   cudaGetSymbolAddress((void**)&p_Wol, g_Wol);
    cudaGetSymbolAddress((void**)&p_W1h, g_W1h);   cudaGetSymbolAddress((void**)&p_W1l, g_W1l);
    cudaGetSymbolAddress((void**)&p_W2h, g_W2h);   cudaGetSymbolAddress((void**)&p_W2l, g_W2l);
    cudaGetSymbolAddress((void**)&p_tn,  g_tn);    cudaGetSymbolAddress((void**)&p_fea, g_fea);
    cudaGetSymbolAddress((void**)&p_kv,  g_kv);    cudaGetSymbolAddress((void**)&p_base,g_base);

    // prep
    int zc = (NB*QROWS*VD*2)/16;
    k_zero4<<<(zc+255)/256, 256>>>((uint4*)p_fbh, zc);
    k_zero4<<<(zc+255)/256, 256>>>((uint4*)p_fbl, zc);
    k_init<<<dim3(16,8,32), 256>>>(feature);
    k_split_convw<<<(9*VD*VD+255)/256, 256>>>(mconv_w);
    k_splitw<<<(2*VD*VD+255)/256, 256>>>(p_Wkvh, p_Wkvl, in_proj_w + VD*VD, 2*VD*VD);
    k_splitw<<<(VD*VD+255)/256, 256>>>(p_Woh, p_Wol, out_proj_w, VD*VD);
    k_splitw<<<(VD*VD+255)/256, 256>>>(p_W1h, p_W1l, lin1_w, VD*VD);
    k_splitw<<<(VD*VD+255)/256, 256>>>(p_W2h, p_W2l, lin2_w, VD*VD);
    k_whs<<<(9*VD*HND+255)/256, 256>>>(mconv_w);
    k_hnp<<<(NB*VD*9+255)/256, 256>>>(hn);
    k_spart<<<(VD*PPOS+255)/256, 256>>>(mconv_w);
    k_base<<<MR*VD/256, 256>>>();

    for (int s=0; s<SEQL; s++){
        k_qh<<<NB, 256>>>(embedding, qconv_w, qconv_b, in_proj_w, in_proj_b, s);
        k_gm<0><<<128, 512, SMEMSZ>>>(p_fbh, p_fbl, p_Wcbh, p_Wcbl,
            nullptr, mnorm_g, mnorm_b, p_base, p_tn, p_tnh, p_tnl, nullptr, s);
        k_gm<1><<<dim3(128,2), 512, SMEMSZ>>>(p_tnh, p_tnl, p_Wkvh, p_Wkvl,
            in_proj_b + VD, nullptr, nullptr, nullptr, p_kv, nullptr, nullptr, nullptr, s);
        k_attn<<<PPOS, 256>>>();
        k_gm<2><<<128, 512, SMEMSZ>>>(p_oh, p_ol, p_Woh, p_Wol,
            out_proj_b, norm_g, norm_b, p_tn, p_fea, p_feah, p_feal, nullptr, s);
        k_gm<3><<<128, 512, SMEMSZ>>>(p_feah, p_feal, p_W1h, p_W1l,
            lin1_b, nullptr, nullptr, nullptr, nullptr, p_f1h, p_f1l, nullptr, s);
        k_gm<4><<<128, 512, SMEMSZ>>>(p_f1h, p_f1l, p_W2h, p_W2l,
            lin2_b, normf_g, normf_b, p_fea, nullptr, nullptr, nullptr, words, s);
    }
    k_copyout<<<dim3(16,8,32), 256>>>((float*)d_out);
}